// round 1
// baseline (speedup 1.0000x reference)
#include <cuda_runtime.h>
#include <cstdint>
#include <math.h>

#define SEQ   128
#define BATCH 32
#define EDIM  300
#define HID   200
#define NTAG  17
#define ROWS  (SEQ*BATCH)   // 4096
#define GN    1600          // 2 dirs * 4 gates * 200
#define NCD   50            // CTAs per direction in recurrent kernel

// ---------------- scratch (static device allocations) ----------------
__device__ float d_X0[ROWS*EDIM];    // gathered embeddings      (4096 x 300)
__device__ float d_G0[ROWS*GN];      // layer0 input projections (4096 x 1600)
__device__ float d_H0[ROWS*400];     // layer0 output            (4096 x 400)
__device__ float d_G1[ROWS*GN];      // layer1 input projections
__device__ float d_H1[ROWS*400];     // layer1 output
__device__ unsigned g_cnt[4];        // grid-barrier counters (layer*2 + dir)

__device__ __forceinline__ float sigmoidf_(float x) {
    return 1.0f / (1.0f + expf(-x));
}

// ---------------- counter reset ----------------
__global__ void reset_cnt_kernel() {
    if (threadIdx.x < 4) g_cnt[threadIdx.x] = 0u;
}

// ---------------- embedding gather: X0[t*32+b][e] = emb[words[b][t]][e] ----------------
__global__ void gather_kernel(const int* __restrict__ words,
                              const float* __restrict__ emb) {
    int idx = blockIdx.x * blockDim.x + threadIdx.x;
    if (idx >= ROWS * EDIM) return;
    int row = idx / EDIM;
    int e   = idx - row * EDIM;
    int t = row >> 5;        // row = t*32 + b
    int b = row & 31;
    int w = words[b * SEQ + t];
    d_X0[idx] = emb[(size_t)w * EDIM + e];
}

// ---------------- fp32 GEMM: C[M,N] = A[M,K] @ W[N,K]^T + bias[N] ----------------
// Tiles: BM=128, BN=64, BK=8; 256 threads; thread tile 8x4.
__global__ __launch_bounds__(256)
void sgemm_bias_kernel(const float* __restrict__ A, const float* __restrict__ W,
                       const float* __restrict__ bias, float* __restrict__ C,
                       int M, int N, int K) {
    __shared__ float As[8][128];
    __shared__ float Bs[8][64];

    int tid = threadIdx.x;
    int tx = tid & 15;            // 0..15 -> n block of 4
    int ty = tid >> 4;            // 0..15 -> m block of 8
    int m0 = blockIdx.y * 128;
    int n0 = blockIdx.x * 64;

    float acc[8][4];
#pragma unroll
    for (int i = 0; i < 8; i++)
#pragma unroll
        for (int j = 0; j < 4; j++) acc[i][j] = 0.f;

    int arow = tid >> 1;          // 0..127
    int ak   = (tid & 1) * 4;     // 0 or 4
    int brow = tid >> 2;          // 0..63
    int bk   = (tid & 3) * 2;     // 0,2,4,6

    const float* Arow = A + (size_t)(m0 + arow) * K;
    const float* Wrow = W + (size_t)(n0 + brow) * K;

    for (int k0 = 0; k0 < K; k0 += 8) {
#pragma unroll
        for (int j = 0; j < 4; j++) {
            int k = k0 + ak + j;
            As[ak + j][arow] = (k < K) ? Arow[k] : 0.f;
        }
#pragma unroll
        for (int j = 0; j < 2; j++) {
            int k = k0 + bk + j;
            Bs[bk + j][brow] = (k < K) ? Wrow[k] : 0.f;
        }
        __syncthreads();
#pragma unroll
        for (int kk = 0; kk < 8; kk++) {
            float4 bv = *(const float4*)&Bs[kk][tx * 4];
            float4 a0 = *(const float4*)&As[kk][ty * 8];
            float4 a1 = *(const float4*)&As[kk][ty * 8 + 4];
            float am[8] = {a0.x, a0.y, a0.z, a0.w, a1.x, a1.y, a1.z, a1.w};
            float bn[4] = {bv.x, bv.y, bv.z, bv.w};
#pragma unroll
            for (int i = 0; i < 8; i++)
#pragma unroll
                for (int j = 0; j < 4; j++)
                    acc[i][j] = fmaf(am[i], bn[j], acc[i][j]);
        }
        __syncthreads();
    }

    float4 bb = *(const float4*)&bias[n0 + tx * 4];
#pragma unroll
    for (int i = 0; i < 8; i++) {
        int m = m0 + ty * 8 + i;
        float4 v;
        v.x = acc[i][0] + bb.x;
        v.y = acc[i][1] + bb.y;
        v.z = acc[i][2] + bb.z;
        v.w = acc[i][3] + bb.w;
        *(float4*)&C[(size_t)m * N + n0 + tx * 4] = v;
    }
}

// ---------------- persistent bidirectional LSTM layer ----------------
// G:   [4096][1600] precomputed x@W.T + b, layout [t*32+b][dir*800 + gate*200 + j]
// Whh: [2][800][200]
// H:   [4096][400] output, layout [t*32+b][dir*200 + j]
// cnt: 2 counters (one per direction)
__global__ __launch_bounds__(256, 1)
void lstm_layer_kernel(const float* __restrict__ G, const float* __restrict__ Whh,
                       float* __restrict__ H, unsigned* cnt) {
    __shared__ float sh_U[16 * 200];    // 16 gate-rows for this CTA's 4 h-indices
    __shared__ float sh_h[32 * 202];    // h_prev, padded stride 202 (bank spread, 8B align)
    __shared__ float sh_y[16 * 32];
    __shared__ float sh_c[4 * 32];      // persistent cell state for this CTA's slice

    int tid = threadIdx.x;
    int dir = blockIdx.x / NCD;
    int cb  = blockIdx.x % NCD;
    int j0  = cb * 4;
    unsigned* mycnt = cnt + dir;

    // preload U rows: r = g*4 + q  ->  Whh[dir][g*200 + j0+q][:]
    const float* Ud = Whh + (size_t)dir * 800 * 200;
    for (int idx = tid; idx < 16 * 200; idx += 256) {
        int r = idx / 200, k = idx - r * 200;
        int g = r >> 2, q = r & 3;
        sh_U[idx] = Ud[(size_t)(g * 200 + j0 + q) * 200 + k];
    }
    if (tid < 128) sh_c[tid] = 0.f;
    __syncthreads();

    int b = tid & 31;
    int w = tid >> 5;   // 0..7 -> computes gate-rows w and w+8

    for (int step = 0; step < SEQ; step++) {
        int t = dir ? (SEQ - 1 - step) : step;

        if (step > 0) {
            int tp = dir ? (t + 1) : (t - 1);
            const float* Hp = H + dir * 200;
            for (int idx = tid; idx < 32 * 50; idx += 256) {
                int bb = idx / 50;
                int j4 = (idx - bb * 50) * 4;
                float4 v = __ldcg((const float4*)&Hp[(size_t)(tp * 32 + bb) * 400 + j4]);
                float* dst = &sh_h[bb * 202 + j4];
                dst[0] = v.x; dst[1] = v.y; dst[2] = v.z; dst[3] = v.w;
            }
        }
        __syncthreads();

        float y0, y1;
        if (step > 0) {
            const unsigned long long* ph  = (const unsigned long long*)(sh_h + b * 202);
            const unsigned long long* pu0 = (const unsigned long long*)(sh_U + w * 200);
            const unsigned long long* pu1 = (const unsigned long long*)(sh_U + (w + 8) * 200);
            unsigned long long acc0 = 0ull, acc1 = 0ull;  // packed {0.f, 0.f}
#pragma unroll 5
            for (int kk = 0; kk < 100; kk++) {
                unsigned long long hv = ph[kk];
                asm("fma.rn.f32x2 %0, %1, %2, %3;" : "=l"(acc0) : "l"(pu0[kk]), "l"(hv), "l"(acc0));
                asm("fma.rn.f32x2 %0, %1, %2, %3;" : "=l"(acc1) : "l"(pu1[kk]), "l"(hv), "l"(acc1));
            }
            float2 a0, a1;
            a0 = *(float2*)&acc0;
            a1 = *(float2*)&acc1;
            y0 = a0.x + a0.y;
            y1 = a1.x + a1.y;
        } else {
            y0 = 0.f; y1 = 0.f;
        }
        sh_y[w * 32 + b] = y0;
        sh_y[(w + 8) * 32 + b] = y1;
        __syncthreads();

        if (tid < 128) {
            int q  = tid >> 5;
            int bb = tid & 31;
            int j = j0 + q;
            int row = t * 32 + bb;
            const float* Gp = G + (size_t)row * GN + dir * 800 + j;
            float yi = sh_y[(0 * 4 + q) * 32 + bb] + Gp[0];
            float yf = sh_y[(1 * 4 + q) * 32 + bb] + Gp[200];
            float yg = sh_y[(2 * 4 + q) * 32 + bb] + Gp[400];
            float yo = sh_y[(3 * 4 + q) * 32 + bb] + Gp[600];
            float c = sigmoidf_(yf) * sh_c[q * 32 + bb] + sigmoidf_(yi) * tanhf(yg);
            float hn = sigmoidf_(yo) * tanhf(c);
            sh_c[q * 32 + bb] = c;
            H[(size_t)row * 400 + dir * 200 + j] = hn;
        }
        __syncthreads();

        if (step < SEQ - 1) {
            if (tid == 0) {
                __threadfence();
                asm volatile("red.release.gpu.global.add.u32 [%0], 1;" :: "l"(mycnt) : "memory");
                unsigned target = (unsigned)NCD * (unsigned)(step + 1);
                unsigned v;
                do {
                    asm volatile("ld.global.acquire.gpu.u32 %0, [%1];" : "=r"(v) : "l"(mycnt) : "memory");
                } while (v < target);
            }
            __syncthreads();
        }
    }
}

// ---------------- output head: sigmoid(H1 @ out_w.T + out_b), (B,S,17) ----------------
__global__ void out_kernel(const float* __restrict__ ow, const float* __restrict__ ob,
                           float* __restrict__ out) {
    int row  = blockIdx.x;           // = s*32 + b
    int warp = threadIdx.x >> 5;     // 0..16 = tag
    int lane = threadIdx.x & 31;
    const float* h    = d_H1 + (size_t)row * 400;
    const float* wrow = ow + warp * 400;
    float sum = 0.f;
#pragma unroll
    for (int k = lane; k < 400; k += 32) sum = fmaf(h[k], wrow[k], sum);
#pragma unroll
    for (int o = 16; o; o >>= 1) sum += __shfl_down_sync(0xffffffffu, sum, o);
    if (lane == 0) {
        int s = row >> 5, b = row & 31;
        out[((size_t)b * SEQ + s) * NTAG + warp] = sigmoidf_(sum + ob[warp]);
    }
}

// ---------------- launch ----------------
extern "C" void kernel_launch(void* const* d_in, const int* in_sizes, int n_in,
                              void* d_out, int out_size) {
    const int*   words = (const int*)  d_in[0];
    const float* emb   = (const float*)d_in[3];
    const float* Wih0  = (const float*)d_in[7];
    const float* Whh0  = (const float*)d_in[8];
    const float* b0    = (const float*)d_in[9];
    const float* Wih1  = (const float*)d_in[10];
    const float* Whh1  = (const float*)d_in[11];
    const float* b1    = (const float*)d_in[12];
    const float* ow    = (const float*)d_in[13];
    const float* ob    = (const float*)d_in[14];
    float* out = (float*)d_out;

    float *pX0, *pG0, *pH0, *pG1, *pH1;
    unsigned* pcnt;
    cudaGetSymbolAddress((void**)&pX0, d_X0);
    cudaGetSymbolAddress((void**)&pG0, d_G0);
    cudaGetSymbolAddress((void**)&pH0, d_H0);
    cudaGetSymbolAddress((void**)&pG1, d_G1);
    cudaGetSymbolAddress((void**)&pH1, d_H1);
    cudaGetSymbolAddress((void**)&pcnt, g_cnt);

    reset_cnt_kernel<<<1, 32>>>();

    gather_kernel<<<(ROWS * EDIM + 255) / 256, 256>>>(words, emb);

    dim3 gdim0(GN / 64, ROWS / 128);
    sgemm_bias_kernel<<<gdim0, 256>>>(pX0, Wih0, b0, pG0, ROWS, GN, EDIM);

    lstm_layer_kernel<<<2 * NCD, 256>>>(pG0, Whh0, pH0, pcnt + 0);

    sgemm_bias_kernel<<<gdim0, 256>>>(pH0, Wih1, b1, pG1, ROWS, GN, 400);

    lstm_layer_kernel<<<2 * NCD, 256>>>(pG1, Whh1, pH1, pcnt + 2);

    out_kernel<<<ROWS, NTAG * 32>>>(ow, ob, out);
}

// round 2
// speedup vs baseline: 1.1103x; 1.1103x over previous
#include <cuda_runtime.h>
#include <cstdint>
#include <math.h>

#define SEQ   128
#define BATCH 32
#define EDIM  300
#define HID   200
#define NTAG  17
#define ROWS  (SEQ*BATCH)   // 4096
#define GN    1600          // 2 dirs * 4 gates * 200
#define NCD   50            // CTAs per direction in recurrent kernel
#define LTHREADS 512

// ---------------- scratch (static device allocations) ----------------
__device__ float d_X0[ROWS*EDIM];    // gathered embeddings      (4096 x 300)
__device__ float d_G0[ROWS*GN];      // layer0 input projections (4096 x 1600)
__device__ float d_H0[ROWS*400];     // layer0 output            (4096 x 400)
__device__ float d_G1[ROWS*GN];      // layer1 input projections
__device__ float d_H1[ROWS*400];     // layer1 output
__device__ unsigned g_cnt[4];        // grid-barrier counters (layer*2 + dir)

__device__ __forceinline__ float fsig(float x) {
    return __fdividef(1.0f, 1.0f + __expf(-x));
}
__device__ __forceinline__ float ftanh(float x) {
    // tanh(x) = 1 - 2/(exp(2x)+1); exact limits at +-inf
    return 1.0f - __fdividef(2.0f, __expf(2.0f * x) + 1.0f);
}

// ---------------- counter reset ----------------
__global__ void reset_cnt_kernel() {
    if (threadIdx.x < 4) g_cnt[threadIdx.x] = 0u;
}

// ---------------- embedding gather: X0[t*32+b][e] = emb[words[b][t]][e] ----------------
__global__ void gather_kernel(const int* __restrict__ words,
                              const float* __restrict__ emb) {
    int idx = blockIdx.x * blockDim.x + threadIdx.x;
    if (idx >= ROWS * EDIM) return;
    int row = idx / EDIM;
    int e   = idx - row * EDIM;
    int t = row >> 5;        // row = t*32 + b
    int b = row & 31;
    int w = words[b * SEQ + t];
    d_X0[idx] = emb[(size_t)w * EDIM + e];
}

// ---------------- fp32 GEMM: C[M,N] = A[M,K] @ W[N,K]^T + bias[N] ----------------
// Tiles: BM=128, BN=64, BK=8; 256 threads; thread tile 8x4.
__global__ __launch_bounds__(256)
void sgemm_bias_kernel(const float* __restrict__ A, const float* __restrict__ W,
                       const float* __restrict__ bias, float* __restrict__ C,
                       int M, int N, int K) {
    __shared__ float As[8][128];
    __shared__ float Bs[8][64];

    int tid = threadIdx.x;
    int tx = tid & 15;            // 0..15 -> n block of 4
    int ty = tid >> 4;            // 0..15 -> m block of 8
    int m0 = blockIdx.y * 128;
    int n0 = blockIdx.x * 64;

    float acc[8][4];
#pragma unroll
    for (int i = 0; i < 8; i++)
#pragma unroll
        for (int j = 0; j < 4; j++) acc[i][j] = 0.f;

    int arow = tid >> 1;          // 0..127
    int ak   = (tid & 1) * 4;     // 0 or 4
    int brow = tid >> 2;          // 0..63
    int bk   = (tid & 3) * 2;     // 0,2,4,6

    const float* Arow = A + (size_t)(m0 + arow) * K;
    const float* Wrow = W + (size_t)(n0 + brow) * K;

    for (int k0 = 0; k0 < K; k0 += 8) {
#pragma unroll
        for (int j = 0; j < 4; j++) {
            int k = k0 + ak + j;
            As[ak + j][arow] = (k < K) ? Arow[k] : 0.f;
        }
#pragma unroll
        for (int j = 0; j < 2; j++) {
            int k = k0 + bk + j;
            Bs[bk + j][brow] = (k < K) ? Wrow[k] : 0.f;
        }
        __syncthreads();
#pragma unroll
        for (int kk = 0; kk < 8; kk++) {
            float4 bv = *(const float4*)&Bs[kk][tx * 4];
            float4 a0 = *(const float4*)&As[kk][ty * 8];
            float4 a1 = *(const float4*)&As[kk][ty * 8 + 4];
            float am[8] = {a0.x, a0.y, a0.z, a0.w, a1.x, a1.y, a1.z, a1.w};
            float bn[4] = {bv.x, bv.y, bv.z, bv.w};
#pragma unroll
            for (int i = 0; i < 8; i++)
#pragma unroll
                for (int j = 0; j < 4; j++)
                    acc[i][j] = fmaf(am[i], bn[j], acc[i][j]);
        }
        __syncthreads();
    }

    float4 bb = *(const float4*)&bias[n0 + tx * 4];
#pragma unroll
    for (int i = 0; i < 8; i++) {
        int m = m0 + ty * 8 + i;
        float4 v;
        v.x = acc[i][0] + bb.x;
        v.y = acc[i][1] + bb.y;
        v.z = acc[i][2] + bb.z;
        v.w = acc[i][3] + bb.w;
        *(float4*)&C[(size_t)m * N + n0 + tx * 4] = v;
    }
}

// ---------------- persistent bidirectional LSTM layer ----------------
// G:   [4096][1600] precomputed x@W.T + b, layout [t*32+b][dir*800 + gate*200 + j]
// Whh: [2][800][200]
// H:   [4096][400] output, layout [t*32+b][dir*200 + j]
// CTA (dir, cb): owns h columns j0..j0+3 -> 16 gate rows. 512 threads:
//   thread (w = tid>>5 in 0..15, b = tid&31) computes gate-row w for batch b.
#define HSTRIDE 204
__global__ __launch_bounds__(LTHREADS, 1)
void lstm_layer_kernel(const float* __restrict__ G, const float* __restrict__ Whh,
                       float* __restrict__ H, unsigned* cnt) {
    __shared__ __align__(16) float sh_U[16 * 200];      // 16 gate-rows
    __shared__ __align__(16) float sh_h[32 * HSTRIDE];  // h_prev per batch
    __shared__ float sh_y[16 * 32];
    __shared__ float sh_c[4 * 32];                      // cell state slice

    int tid = threadIdx.x;
    int dir = blockIdx.x / NCD;
    int cb  = blockIdx.x % NCD;
    int j0  = cb * 4;
    unsigned* mycnt = cnt + dir;

    // preload U rows: r = g*4 + q  ->  Whh[dir][g*200 + j0+q][:]
    const float* Ud = Whh + (size_t)dir * 800 * 200;
    for (int idx = tid; idx < 16 * 200; idx += LTHREADS) {
        int r = idx / 200, k = idx - r * 200;
        int g = r >> 2, q = r & 3;
        sh_U[idx] = Ud[(size_t)(g * 200 + j0 + q) * 200 + k];
    }
    // zero h (step 0 reads it) and c
    for (int idx = tid; idx < 32 * HSTRIDE; idx += LTHREADS) sh_h[idx] = 0.f;
    if (tid < 128) sh_c[tid] = 0.f;
    __syncthreads();

    int b = tid & 31;
    int w = tid >> 5;   // 0..15 gate-row within CTA
    int q  = tid >> 5;  // epilogue col (tid<128)
    const ulonglong2* pu = (const ulonglong2*)(sh_U + w * 200);
    const ulonglong2* ph = (const ulonglong2*)(sh_h + b * HSTRIDE);

    for (int step = 0; step < SEQ; step++) {
        int t = dir ? (SEQ - 1 - step) : step;

        // --- prefetch G for this step's epilogue (overlaps h-load + matvec) ---
        float gi = 0.f, gf = 0.f, gg = 0.f, go = 0.f;
        if (tid < 128) {
            int row = t * 32 + b;
            const float* Gp = G + (size_t)row * GN + dir * 800 + (j0 + q);
            gi = __ldg(Gp);
            gf = __ldg(Gp + 200);
            gg = __ldg(Gp + 400);
            go = __ldg(Gp + 600);
        }

        // --- load h_{t-1} (published by all CTAs of this dir) ---
        if (step > 0) {
            int tp = dir ? (t + 1) : (t - 1);
            const float* Hp = H + dir * 200;
            for (int idx = tid; idx < 32 * 50; idx += LTHREADS) {
                int bb = idx / 50;
                int j4 = (idx - bb * 50) * 4;
                float4 v = __ldcg((const float4*)&Hp[(size_t)(tp * 32 + bb) * 400 + j4]);
                *(float4*)&sh_h[bb * HSTRIDE + j4] = v;
            }
        }
        __syncthreads();

        // --- matvec: y[w] = U[w][:] . h[b][:]  (200 k, 4 per iter) ---
        unsigned long long a0 = 0ull, a1 = 0ull;
#pragma unroll
        for (int kk = 0; kk < 50; kk++) {
            ulonglong2 hv = ph[kk];
            ulonglong2 uv = pu[kk];
            asm("fma.rn.f32x2 %0, %1, %2, %3;" : "=l"(a0) : "l"(uv.x), "l"(hv.x), "l"(a0));
            asm("fma.rn.f32x2 %0, %1, %2, %3;" : "=l"(a1) : "l"(uv.y), "l"(hv.y), "l"(a1));
        }
        float2 f0 = *(float2*)&a0;
        float2 f1 = *(float2*)&a1;
        sh_y[w * 32 + b] = (f0.x + f0.y) + (f1.x + f1.y);
        __syncthreads();

        // --- epilogue: gates -> c,h; publish h slice ---
        if (tid < 128) {
            int row = t * 32 + b;
            float yi = sh_y[(0 * 4 + q) * 32 + b] + gi;
            float yf = sh_y[(1 * 4 + q) * 32 + b] + gf;
            float yg = sh_y[(2 * 4 + q) * 32 + b] + gg;
            float yo = sh_y[(3 * 4 + q) * 32 + b] + go;
            float c = fsig(yf) * sh_c[q * 32 + b] + fsig(yi) * ftanh(yg);
            float hn = fsig(yo) * ftanh(c);
            sh_c[q * 32 + b] = c;
            H[(size_t)row * 400 + dir * 200 + (j0 + q)] = hn;
        }
        __syncthreads();

        // --- grid barrier across this direction's 50 CTAs ---
        if (step < SEQ - 1) {
            if (tid == 0) {
                asm volatile("red.release.gpu.global.add.u32 [%0], 1;" :: "l"(mycnt) : "memory");
                unsigned target = (unsigned)NCD * (unsigned)(step + 1);
                unsigned v;
                do {
                    asm volatile("ld.global.acquire.gpu.u32 %0, [%1];" : "=r"(v) : "l"(mycnt) : "memory");
                } while (v < target);
            }
            __syncthreads();
        }
    }
}

// ---------------- output head: sigmoid(H1 @ out_w.T + out_b), (B,S,17) ----------------
__global__ void out_kernel(const float* __restrict__ ow, const float* __restrict__ ob,
                           float* __restrict__ out) {
    int row  = blockIdx.x;           // = s*32 + b
    int warp = threadIdx.x >> 5;     // 0..16 = tag
    int lane = threadIdx.x & 31;
    const float* h    = d_H1 + (size_t)row * 400;
    const float* wrow = ow + warp * 400;
    float sum = 0.f;
#pragma unroll
    for (int k = lane; k < 400; k += 32) sum = fmaf(h[k], wrow[k], sum);
#pragma unroll
    for (int o = 16; o; o >>= 1) sum += __shfl_down_sync(0xffffffffu, sum, o);
    if (lane == 0) {
        int s = row >> 5, b = row & 31;
        out[((size_t)b * SEQ + s) * NTAG + warp] = fsig(sum + ob[warp]);
    }
}

// ---------------- launch ----------------
extern "C" void kernel_launch(void* const* d_in, const int* in_sizes, int n_in,
                              void* d_out, int out_size) {
    const int*   words = (const int*)  d_in[0];
    const float* emb   = (const float*)d_in[3];
    const float* Wih0  = (const float*)d_in[7];
    const float* Whh0  = (const float*)d_in[8];
    const float* b0    = (const float*)d_in[9];
    const float* Wih1  = (const float*)d_in[10];
    const float* Whh1  = (const float*)d_in[11];
    const float* b1    = (const float*)d_in[12];
    const float* ow    = (const float*)d_in[13];
    const float* ob    = (const float*)d_in[14];
    float* out = (float*)d_out;

    float *pX0, *pG0, *pH0, *pG1, *pH1;
    unsigned* pcnt;
    cudaGetSymbolAddress((void**)&pX0, d_X0);
    cudaGetSymbolAddress((void**)&pG0, d_G0);
    cudaGetSymbolAddress((void**)&pH0, d_H0);
    cudaGetSymbolAddress((void**)&pG1, d_G1);
    cudaGetSymbolAddress((void**)&pH1, d_H1);
    cudaGetSymbolAddress((void**)&pcnt, g_cnt);

    reset_cnt_kernel<<<1, 32>>>();

    gather_kernel<<<(ROWS * EDIM + 255) / 256, 256>>>(words, emb);

    dim3 gdim0(GN / 64, ROWS / 128);
    sgemm_bias_kernel<<<gdim0, 256>>>(pX0, Wih0, b0, pG0, ROWS, GN, EDIM);

    lstm_layer_kernel<<<2 * NCD, LTHREADS>>>(pG0, Whh0, pH0, pcnt + 0);

    sgemm_bias_kernel<<<gdim0, 256>>>(pH0, Wih1, b1, pG1, ROWS, GN, 400);

    lstm_layer_kernel<<<2 * NCD, LTHREADS>>>(pG1, Whh1, pH1, pcnt + 2);

    out_kernel<<<ROWS, NTAG * 32>>>(ow, ob, out);
}

// round 3
// speedup vs baseline: 1.3324x; 1.2000x over previous
#include <cuda_runtime.h>
#include <cstdint>
#include <math.h>

#define SEQ   128
#define BATCH 32
#define EDIM  300
#define HID   200
#define NTAG  17
#define ROWS  (SEQ*BATCH)   // 4096
#define GN    1600          // 2 dirs * 4 gates * 200
#define NCD   50            // CTAs per direction in recurrent kernel
#define LTHREADS 512

typedef unsigned long long ull;

#define FFMA2(acc, a, b) asm("fma.rn.f32x2 %0, %1, %2, %3;" : "=l"(acc) : "l"(a), "l"(b), "l"(acc))
#define SPLAT2(dst, f)   asm("mov.b64 %0, {%1, %1};" : "=l"(dst) : "r"(__float_as_uint(f)))

// ---------------- scratch (static device allocations) ----------------
__device__ float d_X0[ROWS*EDIM];    // gathered embeddings      (4096 x 300)
__device__ float d_G0[ROWS*GN];      // layer0 input projections (4096 x 1600)
__device__ float d_H0[ROWS*400];     // layer0 output            (4096 x 400)
__device__ float d_G1[ROWS*GN];      // layer1 input projections
__device__ float d_H1[ROWS*400];     // layer1 output
__device__ unsigned g_cnt[4];        // grid-barrier counters (layer*2 + dir)

__device__ __forceinline__ float fsig(float x) {
    return __fdividef(1.0f, 1.0f + __expf(-x));
}
__device__ __forceinline__ float ftanh(float x) {
    return 1.0f - __fdividef(2.0f, __expf(2.0f * x) + 1.0f);
}
// swizzled word base of h row b: all even b (and all odd b) land in 16 distinct 8B banks
__device__ __forceinline__ int hbase(int b) { return b * 208 + ((b >> 1) << 1); }
#define HWORDS 6688   // hbase(31)+200 = 6678, padded

// ---------------- counter reset ----------------
__global__ void reset_cnt_kernel() {
    if (threadIdx.x < 4) g_cnt[threadIdx.x] = 0u;
}

// ---------------- embedding gather ----------------
__global__ void gather_kernel(const int* __restrict__ words,
                              const float* __restrict__ emb) {
    int idx = blockIdx.x * blockDim.x + threadIdx.x;
    if (idx >= ROWS * EDIM) return;
    int row = idx / EDIM;
    int e   = idx - row * EDIM;
    int t = row >> 5;
    int b = row & 31;
    int w = words[b * SEQ + t];
    d_X0[idx] = emb[(size_t)w * EDIM + e];
}

// ---------------- fp32 GEMM with FFMA2: C = A @ W^T + bias ----------------
__global__ __launch_bounds__(256)
void sgemm_bias_kernel(const float* __restrict__ A, const float* __restrict__ W,
                       const float* __restrict__ bias, float* __restrict__ C,
                       int M, int N, int K) {
    __shared__ __align__(16) float As[8][128];
    __shared__ __align__(16) float Bs[8][64];

    int tid = threadIdx.x;
    int tx = tid & 15;
    int ty = tid >> 4;
    int m0 = blockIdx.y * 128;
    int n0 = blockIdx.x * 64;

    ull acc2[4][4];   // [m-pair][n], packed over 2 m rows
#pragma unroll
    for (int p = 0; p < 4; p++)
#pragma unroll
        for (int j = 0; j < 4; j++) acc2[p][j] = 0ull;

    int arow = tid >> 1;
    int ak   = (tid & 1) * 4;
    int brow = tid >> 2;
    int bk   = (tid & 3) * 2;

    const float* Arow = A + (size_t)(m0 + arow) * K;
    const float* Wrow = W + (size_t)(n0 + brow) * K;

    for (int k0 = 0; k0 < K; k0 += 8) {
#pragma unroll
        for (int j = 0; j < 4; j++) {
            int k = k0 + ak + j;
            As[ak + j][arow] = (k < K) ? Arow[k] : 0.f;
        }
#pragma unroll
        for (int j = 0; j < 2; j++) {
            int k = k0 + bk + j;
            Bs[bk + j][brow] = (k < K) ? Wrow[k] : 0.f;
        }
        __syncthreads();
#pragma unroll
        for (int kk = 0; kk < 8; kk++) {
            const ulonglong2* ap = (const ulonglong2*)&As[kk][ty * 8];
            ulonglong2 apA = ap[0], apB = ap[1];
            ull am2[4] = {apA.x, apA.y, apB.x, apB.y};
            float4 bv = *(const float4*)&Bs[kk][tx * 4];
            ull bs2[4];
            SPLAT2(bs2[0], bv.x); SPLAT2(bs2[1], bv.y);
            SPLAT2(bs2[2], bv.z); SPLAT2(bs2[3], bv.w);
#pragma unroll
            for (int p = 0; p < 4; p++)
#pragma unroll
                for (int j = 0; j < 4; j++)
                    FFMA2(acc2[p][j], am2[p], bs2[j]);
        }
        __syncthreads();
    }

    float4 bb = *(const float4*)&bias[n0 + tx * 4];
    float bn[4] = {bb.x, bb.y, bb.z, bb.w};
#pragma unroll
    for (int i = 0; i < 8; i++) {
        int m = m0 + ty * 8 + i;
        float4 v;
        float2 f0 = *((float2*)&acc2[i >> 1][0]);
        float2 f1 = *((float2*)&acc2[i >> 1][1]);
        float2 f2 = *((float2*)&acc2[i >> 1][2]);
        float2 f3 = *((float2*)&acc2[i >> 1][3]);
        v.x = ((i & 1) ? f0.y : f0.x) + bn[0];
        v.y = ((i & 1) ? f1.y : f1.x) + bn[1];
        v.z = ((i & 1) ? f2.y : f2.x) + bn[2];
        v.w = ((i & 1) ? f3.y : f3.x) + bn[3];
        *(float4*)&C[(size_t)m * N + n0 + tx * 4] = v;
    }
}

// ---------------- persistent bidirectional LSTM layer ----------------
// CTA (dir, cb): owns h cols j0..j0+3 -> 16 gate rows, all 32 batches.
// Thread decode: bp=tid&15 (b pair), rp=(tid>>4)&7 (row pair), kq=tid>>7 (k quarter).
// Each thread: 2 rows x 2 batches over K/4=50, partials combined via sh_part.
__global__ __launch_bounds__(LTHREADS, 1)
void lstm_layer_kernel(const float* __restrict__ G, const float* __restrict__ Whh,
                       float* __restrict__ H, unsigned* cnt) {
    __shared__ __align__(16) float sh_U[16 * 200];     // 12800 B
    __shared__ __align__(16) float sh_h[HWORDS];       // 26752 B (swizzled rows)
    __shared__ float sh_part[4 * 528];                 // 8448 B (stride 33)

    int tid = threadIdx.x;
    int dir = blockIdx.x / NCD;
    int cb  = blockIdx.x % NCD;
    int j0  = cb * 4;
    unsigned* mycnt = cnt + dir;

    // preload U rows: local row r -> Whh[dir][(r>>2)*200 + j0 + (r&3)][:]
    const float* Ud = Whh + (size_t)dir * 800 * 200;
    for (int idx = tid; idx < 16 * 200; idx += LTHREADS) {
        int r = idx / 200, k = idx - r * 200;
        int g = r >> 2, q = r & 3;
        sh_U[idx] = Ud[(size_t)(g * 200 + j0 + q) * 200 + k];
    }
    for (int idx = tid; idx < HWORDS; idx += LTHREADS) sh_h[idx] = 0.f;
    __syncthreads();

    int bp = tid & 15;
    int rp = (tid >> 4) & 7;
    int kq = tid >> 7;
    int b0 = 2 * bp, b1 = b0 + 1;
    int r0 = 2 * rp, r1 = r0 + 1;

    const ull* pu0 = (const ull*)(sh_U + r0 * 200) + kq * 25;
    const ull* pu1 = (const ull*)(sh_U + r1 * 200) + kq * 25;
    const ull* ph0 = (const ull*)(sh_h + hbase(b0)) + kq * 25;
    const ull* ph1 = (const ull*)(sh_h + hbase(b1)) + kq * 25;

    // epilogue thread identity (tid < 128): col q, batch b
    int eq = tid >> 5;
    int eb = tid & 31;
    float creg = 0.f;                       // cell state in registers
    const float* Gbase = G + dir * 800 + (j0 + eq) + (size_t)eb * GN;

    for (int step = 0; step < SEQ; step++) {
        int t = dir ? (SEQ - 1 - step) : step;

        // prefetch G for epilogue (overlaps h fill + matvec)
        float gi = 0.f, gf = 0.f, gg = 0.f, go = 0.f;
        if (tid < 128) {
            const float* Gp = Gbase + (size_t)t * (32 * GN);
            gi = __ldg(Gp);
            gf = __ldg(Gp + 200);
            gg = __ldg(Gp + 400);
            go = __ldg(Gp + 600);
        }

        // load h_{t-1} into swizzled smem
        if (step > 0) {
            int tp = dir ? (t + 1) : (t - 1);
            const float* Hp = H + dir * 200;
            for (int idx = tid; idx < 32 * 50; idx += LTHREADS) {
                int bb = idx / 50;
                int j4 = (idx - bb * 50) * 4;
                float4 v = __ldcg((const float4*)&Hp[(size_t)(tp * 32 + bb) * 400 + j4]);
                ull* dst = (ull*)(sh_h + hbase(bb) + j4);
                dst[0] = ((ull*)&v)[0];
                dst[1] = ((ull*)&v)[1];
            }
        }
        __syncthreads();

        // matvec: 2 rows x 2 batches, K-slice of 50 (25 u64 pairs)
        ull a00 = 0ull, a01 = 0ull, a10 = 0ull, a11 = 0ull;
#pragma unroll
        for (int kk = 0; kk < 25; kk++) {
            ull h0v = ph0[kk];
            ull h1v = ph1[kk];
            ull u0v = pu0[kk];
            ull u1v = pu1[kk];
            FFMA2(a00, u0v, h0v);
            FFMA2(a01, u0v, h1v);
            FFMA2(a10, u1v, h0v);
            FFMA2(a11, u1v, h1v);
        }
        {
            float2 f;
            float* P = sh_part + kq * 528;
            f = *(float2*)&a00; P[r0 * 33 + b0] = f.x + f.y;
            f = *(float2*)&a01; P[r0 * 33 + b1] = f.x + f.y;
            f = *(float2*)&a10; P[r1 * 33 + b0] = f.x + f.y;
            f = *(float2*)&a11; P[r1 * 33 + b1] = f.x + f.y;
        }
        __syncthreads();

        // epilogue: combine partials, gates -> c,h; publish h slice
        if (tid < 128) {
            float y[4];
#pragma unroll
            for (int g = 0; g < 4; g++) {
                int r = 4 * g + eq;
                y[g] = sh_part[0 * 528 + r * 33 + eb] + sh_part[1 * 528 + r * 33 + eb]
                     + sh_part[2 * 528 + r * 33 + eb] + sh_part[3 * 528 + r * 33 + eb];
            }
            float yi = y[0] + gi;
            float yf = y[1] + gf;
            float yg = y[2] + gg;
            float yo = y[3] + go;
            float c = fsig(yf) * creg + fsig(yi) * ftanh(yg);
            float hn = fsig(yo) * ftanh(c);
            creg = c;
            H[(size_t)(t * 32 + eb) * 400 + dir * 200 + (j0 + eq)] = hn;
        }
        __syncthreads();

        // grid barrier across this direction's 50 CTAs
        if (step < SEQ - 1) {
            if (tid == 0) {
                asm volatile("red.release.gpu.global.add.u32 [%0], 1;" :: "l"(mycnt) : "memory");
                unsigned target = (unsigned)NCD * (unsigned)(step + 1);
                unsigned v;
                do {
                    asm volatile("ld.global.acquire.gpu.u32 %0, [%1];" : "=r"(v) : "l"(mycnt) : "memory");
                } while (v < target);
            }
            __syncthreads();
        }
    }
}

// ---------------- output head ----------------
__global__ void out_kernel(const float* __restrict__ ow, const float* __restrict__ ob,
                           float* __restrict__ out) {
    int row  = blockIdx.x;           // = s*32 + b
    int warp = threadIdx.x >> 5;     // 0..16 = tag
    int lane = threadIdx.x & 31;
    const float* h    = d_H1 + (size_t)row * 400;
    const float* wrow = ow + warp * 400;
    float sum = 0.f;
#pragma unroll
    for (int k = lane; k < 400; k += 32) sum = fmaf(h[k], wrow[k], sum);
#pragma unroll
    for (int o = 16; o; o >>= 1) sum += __shfl_down_sync(0xffffffffu, sum, o);
    if (lane == 0) {
        int s = row >> 5, b = row & 31;
        out[((size_t)b * SEQ + s) * NTAG + warp] = fsig(sum + ob[warp]);
    }
}

// ---------------- launch ----------------
extern "C" void kernel_launch(void* const* d_in, const int* in_sizes, int n_in,
                              void* d_out, int out_size) {
    const int*   words = (const int*)  d_in[0];
    const float* emb   = (const float*)d_in[3];
    const float* Wih0  = (const float*)d_in[7];
    const float* Whh0  = (const float*)d_in[8];
    const float* b0    = (const float*)d_in[9];
    const float* Wih1  = (const float*)d_in[10];
    const float* Whh1  = (const float*)d_in[11];
    const float* b1    = (const float*)d_in[12];
    const float* ow    = (const float*)d_in[13];
    const float* ob    = (const float*)d_in[14];
    float* out = (float*)d_out;

    float *pX0, *pG0, *pH0, *pG1, *pH1;
    unsigned* pcnt;
    cudaGetSymbolAddress((void**)&pX0, d_X0);
    cudaGetSymbolAddress((void**)&pG0, d_G0);
    cudaGetSymbolAddress((void**)&pH0, d_H0);
    cudaGetSymbolAddress((void**)&pG1, d_G1);
    cudaGetSymbolAddress((void**)&pH1, d_H1);
    cudaGetSymbolAddress((void**)&pcnt, g_cnt);

    reset_cnt_kernel<<<1, 32>>>();

    gather_kernel<<<(ROWS * EDIM + 255) / 256, 256>>>(words, emb);

    dim3 gdim0(GN / 64, ROWS / 128);
    sgemm_bias_kernel<<<gdim0, 256>>>(pX0, Wih0, b0, pG0, ROWS, GN, EDIM);

    lstm_layer_kernel<<<2 * NCD, LTHREADS>>>(pG0, Whh0, pH0, pcnt + 0);

    sgemm_bias_kernel<<<gdim0, 256>>>(pH0, Wih1, b1, pG1, ROWS, GN, 400);

    lstm_layer_kernel<<<2 * NCD, LTHREADS>>>(pG1, Whh1, pH1, pcnt + 2);

    out_kernel<<<ROWS, NTAG * 32>>>(ow, ob, out);
}